// round 15
// baseline (speedup 1.0000x reference)
#include <cuda_runtime.h>
#include <math.h>

#define BB 2
#define TT 2048
#define CC 512
#define NB 4
#define QN (NB*CC)   // 2048
#define HALF (CC/2)  // 256

// Scratch (no cudaMalloc allowed)
__device__ float g_Q[BB*TT*QN];
__device__ float g_K[BB*TT*CC];
__device__ float g_V[BB*TT*QN];
__device__ float g_Y[BB*TT*CC];

// ---------------------------------------------------------------------------
// SGEMM (R1 scalar version, known-good): Out[M,N] = A[M,K] @ W[K,N].
// ---------------------------------------------------------------------------
template<int DO_ROPE>
__global__ void __launch_bounds__(256) gemm_kernel(
    const float* __restrict__ A, const float* __restrict__ W, float* __restrict__ Out,
    int M, int N, int K,
    const float* __restrict__ cosT, const float* __restrict__ sinT, float scale)
{
    constexpr int BM = 128, BN = 64, BK = 16;
    __shared__ float As[BK][BM];
    __shared__ float Ws[BK][BN];

    const int tid = threadIdx.x;
    const int tx = tid & 15;
    const int ty = tid >> 4;
    const int rowBase = blockIdx.y * BM;
    const int colBase = blockIdx.x * BN;

    float acc[8][4];
#pragma unroll
    for (int m = 0; m < 8; m++)
#pragma unroll
        for (int n = 0; n < 4; n++) acc[m][n] = 0.f;

    for (int k0 = 0; k0 < K; k0 += BK) {
#pragma unroll
        for (int i = 0; i < 2; i++) {
            int slot = tid + i * 256;
            int r  = slot >> 2;
            int c4 = (slot & 3) * 4;
            float4 v = *(const float4*)(A + (size_t)(rowBase + r) * K + k0 + c4);
            As[c4 + 0][r] = v.x; As[c4 + 1][r] = v.y;
            As[c4 + 2][r] = v.z; As[c4 + 3][r] = v.w;
        }
        {
            int rr = tid >> 4;
            int c4 = (tid & 15) * 4;
            float4 v = *(const float4*)(W + (size_t)(k0 + rr) * N + colBase + c4);
            *(float4*)&Ws[rr][c4] = v;
        }
        __syncthreads();

#pragma unroll
        for (int kk = 0; kk < BK; kk++) {
            float4 a0 = *(float4*)&As[kk][ty * 8];
            float4 a1 = *(float4*)&As[kk][ty * 8 + 4];
            float4 wv = *(float4*)&Ws[kk][tx * 4];
            float ar[8] = {a0.x, a0.y, a0.z, a0.w, a1.x, a1.y, a1.z, a1.w};
            float wr[4] = {wv.x, wv.y, wv.z, wv.w};
#pragma unroll
            for (int m = 0; m < 8; m++)
#pragma unroll
                for (int n = 0; n < 4; n++) acc[m][n] += ar[m] * wr[n];
        }
        __syncthreads();
    }

    const int gc = colBase + tx * 4;
#pragma unroll
    for (int mI = 0; mI < 8; mI++) {
        int gr = rowBase + ty * 8 + mI;
        float o0 = acc[mI][0], o1 = acc[mI][1], o2 = acc[mI][2], o3 = acc[mI][3];
        if (DO_ROPE) {
            int t   = gr & (TT - 1);
            int cin = gc & (CC - 1);
            int i0  = cin >> 1;
            float c0v = cosT[t * HALF + i0],     s0v = sinT[t * HALF + i0];
            float c1v = cosT[t * HALF + i0 + 1], s1v = sinT[t * HALF + i0 + 1];
            float r0 = o0 * c0v - o1 * s0v;
            float r1 = o0 * s0v + o1 * c0v;
            float r2 = o2 * c1v - o3 * s1v;
            float r3 = o2 * s1v + o3 * c1v;
            o0 = r0; o1 = r1; o2 = r2; o3 = r3;
        }
        float4 out4 = make_float4(o0 * scale, o1 * scale, o2 * scale, o3 * scale);
        *(float4*)(Out + (size_t)gr * N + gc) = out4;
    }
}

// ---------------------------------------------------------------------------
// Fused routed attention, SPLIT-S x4: 2 rows/CTA, 4 warps per row. Within
// each 16-step K tile, warp q of a row takes steps si ≡ q (mod 4). No-max
// softmax sums are associative -> additive 4-way combine at the end.
// Per-warp serial chain is ~1/4 of the R11 baseline.
// ---------------------------------------------------------------------------
__global__ void __launch_bounds__(256, 2) attn_kernel(
    const float* __restrict__ Q, const float* __restrict__ K,
    const float* __restrict__ V, float* __restrict__ Y)
{
    constexpr int SBLK = 16;
    __shared__ float4 ks[SBLK][CC / 4];     // 32KB
    __shared__ float4 redv[2][3][4][32];    // 12KB [row][srcwarp-1][jj][lane]
    __shared__ float  redl[2][3][32];       // 768B

    const int tid   = threadIdx.x;
    const int w     = tid >> 5;
    const int lane  = tid & 31;
    const int rw    = w >> 2;               // 0..1 : row within CTA
    const int quad  = w & 3;                // 0..3 : step phase (si mod 4)
    const int r     = blockIdx.x * 2 + rw;
    const int t     = r & (TT - 1);
    const int tmax  = (blockIdx.x * 2 + 1) & (TT - 1);

    float4 q[NB][4];
    const float* qp = Q + (size_t)r * QN;
#pragma unroll
    for (int n = 0; n < NB; n++)
#pragma unroll
        for (int jj = 0; jj < 4; jj++)
            q[n][jj] = *(const float4*)(qp + n * CC + jj * 128 + lane * 4);

    float4 acc[4];
#pragma unroll
    for (int jj = 0; jj < 4; jj++) acc[jj] = make_float4(0.f, 0.f, 0.f, 0.f);
    float l = 0.f;

    const float* kb = K + (size_t)(r - t) * CC;
    const float* vb = V + (size_t)(r - t) * QN;
    const int b0 = lane & 1;
    const int b1 = (lane >> 1) & 1;

    // score for step si: dots + pair-fold reduce + argmax (warp-uniform out)
    auto score = [&](int si, float& smax, int& nsel) {
        float4 k4[4];
#pragma unroll
        for (int jj = 0; jj < 4; jj++) k4[jj] = ks[si][jj * 32 + lane];
        float d[NB];
#pragma unroll
        for (int n = 0; n < NB; n++) {
            float s = 0.f;
#pragma unroll
            for (int jj = 0; jj < 4; jj++) {
                s += q[n][jj].x * k4[jj].x;
                s += q[n][jj].y * k4[jj].y;
                s += q[n][jj].z * k4[jj].z;
                s += q[n][jj].w * k4[jj].w;
            }
            d[n] = s;
        }
        float sel01  = b0 ? d[0] : d[1];
        float keep01 = b0 ? d[1] : d[0];
        float w01 = keep01 + __shfl_xor_sync(0xffffffffu, sel01, 1);
        float sel23  = b0 ? d[2] : d[3];
        float keep23 = b0 ? d[3] : d[2];
        float w23 = keep23 + __shfl_xor_sync(0xffffffffu, sel23, 1);
        float selq  = b1 ? w01 : w23;
        float keepq = b1 ? w23 : w01;
        float wv = keepq + __shfl_xor_sync(0xffffffffu, selq, 2);
        wv += __shfl_xor_sync(0xffffffffu, wv, 4);
        wv += __shfl_xor_sync(0xffffffffu, wv, 8);
        wv += __shfl_xor_sync(0xffffffffu, wv, 16);
        float v  = wv;
        int   id = lane & 3;
#pragma unroll
        for (int off = 1; off <= 2; off <<= 1) {
            float v1 = __shfl_xor_sync(0xffffffffu, v, off);
            int  id1 = __shfl_xor_sync(0xffffffffu, id, off);
            if (v1 > v || (v1 == v && id1 < id)) { v = v1; id = id1; }
        }
        smax = v; nsel = id;
    };

    for (int s0 = 0; s0 <= tmax; s0 += SBLK) {
        // cooperative K tile load: all 8 warps
#pragma unroll
        for (int i = 0; i < 8; i++) {
            int slot = tid + i * 256;
            int si = slot >> 7, cj = slot & 127;
            ks[si][cj] = *(const float4*)(kb + (size_t)(s0 + si) * CC + cj * 4);
        }
        __syncthreads();

        const float* vs0 = vb + (size_t)s0 * QN;
        int send = t - s0; if (send > SBLK - 1) send = SBLK - 1;

        if (send >= quad) {
            // prologue: first step for this phase
            float smax; int nsel;
            score(quad, smax, nsel);
            float p_cur = __expf(smax);
            const float4* vr = (const float4*)(vs0 + (size_t)quad * QN + (nsel << 9));
            float4 vv[4];
#pragma unroll
            for (int jj = 0; jj < 4; jj++) vv[jj] = vr[jj * 32 + lane];

            // steady state: stride-4 over the tile, V load pipelined
            for (int si = quad + 4; si <= send; si += 4) {
                float smax2; int nsel2;
                score(si, smax2, nsel2);
                l += p_cur;
#pragma unroll
                for (int jj = 0; jj < 4; jj++) {
                    acc[jj].x += p_cur * vv[jj].x;
                    acc[jj].y += p_cur * vv[jj].y;
                    acc[jj].z += p_cur * vv[jj].z;
                    acc[jj].w += p_cur * vv[jj].w;
                }
                p_cur = __expf(smax2);
                vr = (const float4*)(vs0 + (size_t)si * QN + (nsel2 << 9));
#pragma unroll
                for (int jj = 0; jj < 4; jj++) vv[jj] = vr[jj * 32 + lane];
            }

            // epilogue
            l += p_cur;
#pragma unroll
            for (int jj = 0; jj < 4; jj++) {
                acc[jj].x += p_cur * vv[jj].x;
                acc[jj].y += p_cur * vv[jj].y;
                acc[jj].z += p_cur * vv[jj].z;
                acc[jj].w += p_cur * vv[jj].w;
            }
        }
        __syncthreads();
    }

    // ---- 4-way additive combine per row (exact: plain sums) ----
    if (quad != 0) {
#pragma unroll
        for (int jj = 0; jj < 4; jj++) redv[rw][quad - 1][jj][lane] = acc[jj];
        redl[rw][quad - 1][lane] = l;
    }
    __syncthreads();
    if (quad == 0) {
#pragma unroll
        for (int src = 0; src < 3; src++) {
#pragma unroll
            for (int jj = 0; jj < 4; jj++) {
                float4 o = redv[rw][src][jj][lane];
                acc[jj].x += o.x; acc[jj].y += o.y;
                acc[jj].z += o.z; acc[jj].w += o.w;
            }
            l += redl[rw][src][lane];
        }

        float inv = 1.f / l;
        float* yp = Y + (size_t)r * CC;
#pragma unroll
        for (int jj = 0; jj < 4; jj++) {
            float4 o = make_float4(acc[jj].x * inv, acc[jj].y * inv,
                                   acc[jj].z * inv, acc[jj].w * inv);
            *(float4*)(yp + jj * 128 + lane * 4) = o;
        }
    }
}

// ---------------------------------------------------------------------------
extern "C" void kernel_launch(void* const* d_in, const int* in_sizes, int n_in,
                              void* d_out, int out_size)
{
    const float* a    = (const float*)d_in[0];
    const float* x    = (const float*)d_in[1];
    const float* Wq   = (const float*)d_in[2];
    const float* Wk   = (const float*)d_in[3];
    const float* Wv   = (const float*)d_in[4];
    const float* Wo   = (const float*)d_in[5];
    const float* cosT = (const float*)d_in[6];
    const float* sinT = (const float*)d_in[7];
    float* out = (float*)d_out;

    float* Qb; cudaGetSymbolAddress((void**)&Qb, g_Q);
    float* Kb; cudaGetSymbolAddress((void**)&Kb, g_K);
    float* Vb; cudaGetSymbolAddress((void**)&Vb, g_V);
    float* Yb; cudaGetSymbolAddress((void**)&Yb, g_Y);

    const int M = BB * TT;
    const float qscale = 0.04419417382415922f;  // 1/sqrt(512)

    dim3 thr(256);
    gemm_kernel<1><<<dim3(QN / 64, M / 128), thr>>>(a, Wq, Qb, M, QN, CC, cosT, sinT, qscale);
    gemm_kernel<1><<<dim3(CC / 64, M / 128), thr>>>(x, Wk, Kb, M, CC, CC, cosT, sinT, 1.0f);
    gemm_kernel<0><<<dim3(QN / 64, M / 128), thr>>>(a, Wv, Vb, M, QN, CC, nullptr, nullptr, 1.0f);
    attn_kernel<<<M / 2, thr>>>(Qb, Kb, Vb, Yb);
    gemm_kernel<0><<<dim3(CC / 64, M / 128), thr>>>(Yb, Wo, out, M, CC, CC, nullptr, nullptr, 1.0f);
}

// round 16
// speedup vs baseline: 1.1407x; 1.1407x over previous
#include <cuda_runtime.h>
#include <math.h>

#define BB 2
#define TT 2048
#define CC 512
#define NB 4
#define QN (NB*CC)   // 2048
#define HALF (CC/2)  // 256

// Scratch (no cudaMalloc allowed)
__device__ float g_Q[BB*TT*QN];
__device__ float g_K[BB*TT*CC];
__device__ float g_V[BB*TT*QN];
__device__ float g_Y[BB*TT*CC];

// ---------------------------------------------------------------------------
// SGEMM (R1 scalar version, known-good): Out[M,N] = A[M,K] @ W[K,N].
// ---------------------------------------------------------------------------
template<int DO_ROPE>
__global__ void __launch_bounds__(256) gemm_kernel(
    const float* __restrict__ A, const float* __restrict__ W, float* __restrict__ Out,
    int M, int N, int K,
    const float* __restrict__ cosT, const float* __restrict__ sinT, float scale)
{
    constexpr int BM = 128, BN = 64, BK = 16;
    __shared__ float As[BK][BM];
    __shared__ float Ws[BK][BN];

    const int tid = threadIdx.x;
    const int tx = tid & 15;
    const int ty = tid >> 4;
    const int rowBase = blockIdx.y * BM;
    const int colBase = blockIdx.x * BN;

    float acc[8][4];
#pragma unroll
    for (int m = 0; m < 8; m++)
#pragma unroll
        for (int n = 0; n < 4; n++) acc[m][n] = 0.f;

    for (int k0 = 0; k0 < K; k0 += BK) {
#pragma unroll
        for (int i = 0; i < 2; i++) {
            int slot = tid + i * 256;
            int r  = slot >> 2;
            int c4 = (slot & 3) * 4;
            float4 v = *(const float4*)(A + (size_t)(rowBase + r) * K + k0 + c4);
            As[c4 + 0][r] = v.x; As[c4 + 1][r] = v.y;
            As[c4 + 2][r] = v.z; As[c4 + 3][r] = v.w;
        }
        {
            int rr = tid >> 4;
            int c4 = (tid & 15) * 4;
            float4 v = *(const float4*)(W + (size_t)(k0 + rr) * N + colBase + c4);
            *(float4*)&Ws[rr][c4] = v;
        }
        __syncthreads();

#pragma unroll
        for (int kk = 0; kk < BK; kk++) {
            float4 a0 = *(float4*)&As[kk][ty * 8];
            float4 a1 = *(float4*)&As[kk][ty * 8 + 4];
            float4 wv = *(float4*)&Ws[kk][tx * 4];
            float ar[8] = {a0.x, a0.y, a0.z, a0.w, a1.x, a1.y, a1.z, a1.w};
            float wr[4] = {wv.x, wv.y, wv.z, wv.w};
#pragma unroll
            for (int m = 0; m < 8; m++)
#pragma unroll
                for (int n = 0; n < 4; n++) acc[m][n] += ar[m] * wr[n];
        }
        __syncthreads();
    }

    const int gc = colBase + tx * 4;
#pragma unroll
    for (int mI = 0; mI < 8; mI++) {
        int gr = rowBase + ty * 8 + mI;
        float o0 = acc[mI][0], o1 = acc[mI][1], o2 = acc[mI][2], o3 = acc[mI][3];
        if (DO_ROPE) {
            int t   = gr & (TT - 1);
            int cin = gc & (CC - 1);
            int i0  = cin >> 1;
            float c0v = cosT[t * HALF + i0],     s0v = sinT[t * HALF + i0];
            float c1v = cosT[t * HALF + i0 + 1], s1v = sinT[t * HALF + i0 + 1];
            float r0 = o0 * c0v - o1 * s0v;
            float r1 = o0 * s0v + o1 * c0v;
            float r2 = o2 * c1v - o3 * s1v;
            float r3 = o2 * s1v + o3 * c1v;
            o0 = r0; o1 = r1; o2 = r2; o3 = r3;
        }
        float4 out4 = make_float4(o0 * scale, o1 * scale, o2 * scale, o3 * scale);
        *(float4*)(Out + (size_t)gr * N + gc) = out4;
    }
}

// ---------------------------------------------------------------------------
// Fused routed attention, SPLIT-S (R14, best) + LPT block order: blocks are
// mapped to rows in DESCENDING t so the longest causal rows start in wave 0
// and short rows backfill — removes the straggler tail of ascending order.
// 4 rows/CTA, 2 warps per row (even/odd si); no-max softmax, additive combine.
// ---------------------------------------------------------------------------
__global__ void __launch_bounds__(256, 2) attn_kernel(
    const float* __restrict__ Q, const float* __restrict__ K,
    const float* __restrict__ V, float* __restrict__ Y)
{
    constexpr int SBLK = 16;
    __shared__ float4 ks[SBLK][CC / 4];   // 32KB
    __shared__ float4 redv[4][4][32];     // 8KB  [rowpair][jj][lane]
    __shared__ float  redl[4][32];        // 512B

    const int tid   = threadIdx.x;
    const int w     = tid >> 5;
    const int lane  = tid & 31;
    const int pairw = w >> 1;             // 0..3 : row within CTA
    const int half  = w & 1;              // 0/1  : even/odd steps
    const int blk   = gridDim.x - 1 - blockIdx.x;   // LPT: longest rows first
    const int r     = blk * 4 + pairw;
    const int t     = r & (TT - 1);
    const int tmax  = (blk * 4 + 3) & (TT - 1);

    float4 q[NB][4];
    const float* qp = Q + (size_t)r * QN;
#pragma unroll
    for (int n = 0; n < NB; n++)
#pragma unroll
        for (int jj = 0; jj < 4; jj++)
            q[n][jj] = *(const float4*)(qp + n * CC + jj * 128 + lane * 4);

    float4 acc[4];
#pragma unroll
    for (int jj = 0; jj < 4; jj++) acc[jj] = make_float4(0.f, 0.f, 0.f, 0.f);
    float l = 0.f;

    const float* kb = K + (size_t)(r - t) * CC;
    const float* vb = V + (size_t)(r - t) * QN;
    const int b0 = lane & 1;
    const int b1 = (lane >> 1) & 1;

    // score for step si: dots + pair-fold reduce + argmax (warp-uniform out)
    auto score = [&](int si, float& smax, int& nsel) {
        float4 k4[4];
#pragma unroll
        for (int jj = 0; jj < 4; jj++) k4[jj] = ks[si][jj * 32 + lane];
        float d[NB];
#pragma unroll
        for (int n = 0; n < NB; n++) {
            float s = 0.f;
#pragma unroll
            for (int jj = 0; jj < 4; jj++) {
                s += q[n][jj].x * k4[jj].x;
                s += q[n][jj].y * k4[jj].y;
                s += q[n][jj].z * k4[jj].z;
                s += q[n][jj].w * k4[jj].w;
            }
            d[n] = s;
        }
        float sel01  = b0 ? d[0] : d[1];
        float keep01 = b0 ? d[1] : d[0];
        float w01 = keep01 + __shfl_xor_sync(0xffffffffu, sel01, 1);
        float sel23  = b0 ? d[2] : d[3];
        float keep23 = b0 ? d[3] : d[2];
        float w23 = keep23 + __shfl_xor_sync(0xffffffffu, sel23, 1);
        float selq  = b1 ? w01 : w23;
        float keepq = b1 ? w23 : w01;
        float wv = keepq + __shfl_xor_sync(0xffffffffu, selq, 2);
        wv += __shfl_xor_sync(0xffffffffu, wv, 4);
        wv += __shfl_xor_sync(0xffffffffu, wv, 8);
        wv += __shfl_xor_sync(0xffffffffu, wv, 16);
        float v  = wv;
        int   id = lane & 3;
#pragma unroll
        for (int off = 1; off <= 2; off <<= 1) {
            float v1 = __shfl_xor_sync(0xffffffffu, v, off);
            int  id1 = __shfl_xor_sync(0xffffffffu, id, off);
            if (v1 > v || (v1 == v && id1 < id)) { v = v1; id = id1; }
        }
        smax = v; nsel = id;
    };

    for (int s0 = 0; s0 <= tmax; s0 += SBLK) {
        // cooperative K tile load: all 8 warps
#pragma unroll
        for (int i = 0; i < 8; i++) {
            int slot = tid + i * 256;
            int si = slot >> 7, cj = slot & 127;
            ks[si][cj] = *(const float4*)(kb + (size_t)(s0 + si) * CC + cj * 4);
        }
        __syncthreads();

        const float* vs0 = vb + (size_t)s0 * QN;
        int send = t - s0; if (send > SBLK - 1) send = SBLK - 1;

        if (send >= half) {
            // prologue: first step for this half
            float smax; int nsel;
            score(half, smax, nsel);
            float p_cur = __expf(smax);
            const float4* vr = (const float4*)(vs0 + (size_t)half * QN + (nsel << 9));
            float4 vv[4];
#pragma unroll
            for (int jj = 0; jj < 4; jj++) vv[jj] = vr[jj * 32 + lane];

            // steady state: stride-2 over the tile, V load pipelined
            for (int si = half + 2; si <= send; si += 2) {
                float smax2; int nsel2;
                score(si, smax2, nsel2);
                l += p_cur;
#pragma unroll
                for (int jj = 0; jj < 4; jj++) {
                    acc[jj].x += p_cur * vv[jj].x;
                    acc[jj].y += p_cur * vv[jj].y;
                    acc[jj].z += p_cur * vv[jj].z;
                    acc[jj].w += p_cur * vv[jj].w;
                }
                p_cur = __expf(smax2);
                vr = (const float4*)(vs0 + (size_t)si * QN + (nsel2 << 9));
#pragma unroll
                for (int jj = 0; jj < 4; jj++) vv[jj] = vr[jj * 32 + lane];
            }

            // epilogue
            l += p_cur;
#pragma unroll
            for (int jj = 0; jj < 4; jj++) {
                acc[jj].x += p_cur * vv[jj].x;
                acc[jj].y += p_cur * vv[jj].y;
                acc[jj].z += p_cur * vv[jj].z;
                acc[jj].w += p_cur * vv[jj].w;
            }
        }
        __syncthreads();
    }

    // ---- combine the warp pair (exact: plain sums) ----
    if (half == 1) {
#pragma unroll
        for (int jj = 0; jj < 4; jj++) redv[pairw][jj][lane] = acc[jj];
        redl[pairw][lane] = l;
    }
    __syncthreads();
    if (half == 0) {
#pragma unroll
        for (int jj = 0; jj < 4; jj++) {
            float4 o = redv[pairw][jj][lane];
            acc[jj].x += o.x; acc[jj].y += o.y;
            acc[jj].z += o.z; acc[jj].w += o.w;
        }
        l += redl[pairw][lane];

        float inv = 1.f / l;
        float* yp = Y + (size_t)r * CC;
#pragma unroll
        for (int jj = 0; jj < 4; jj++) {
            float4 o = make_float4(acc[jj].x * inv, acc[jj].y * inv,
                                   acc[jj].z * inv, acc[jj].w * inv);
            *(float4*)(yp + jj * 128 + lane * 4) = o;
        }
    }
}

// ---------------------------------------------------------------------------
extern "C" void kernel_launch(void* const* d_in, const int* in_sizes, int n_in,
                              void* d_out, int out_size)
{
    const float* a    = (const float*)d_in[0];
    const float* x    = (const float*)d_in[1];
    const float* Wq   = (const float*)d_in[2];
    const float* Wk   = (const float*)d_in[3];
    const float* Wv   = (const float*)d_in[4];
    const float* Wo   = (const float*)d_in[5];
    const float* cosT = (const float*)d_in[6];
    const float* sinT = (const float*)d_in[7];
    float* out = (float*)d_out;

    float* Qb; cudaGetSymbolAddress((void**)&Qb, g_Q);
    float* Kb; cudaGetSymbolAddress((void**)&Kb, g_K);
    float* Vb; cudaGetSymbolAddress((void**)&Vb, g_V);
    float* Yb; cudaGetSymbolAddress((void**)&Yb, g_Y);

    const int M = BB * TT;
    const float qscale = 0.04419417382415922f;  // 1/sqrt(512)

    dim3 thr(256);
    gemm_kernel<1><<<dim3(QN / 64, M / 128), thr>>>(a, Wq, Qb, M, QN, CC, cosT, sinT, qscale);
    gemm_kernel<1><<<dim3(CC / 64, M / 128), thr>>>(x, Wk, Kb, M, CC, CC, cosT, sinT, 1.0f);
    gemm_kernel<0><<<dim3(QN / 64, M / 128), thr>>>(a, Wv, Vb, M, QN, CC, nullptr, nullptr, 1.0f);
    attn_kernel<<<M / 4, thr>>>(Qb, Kb, Vb, Yb);
    gemm_kernel<0><<<dim3(CC / 64, M / 128), thr>>>(Yb, Wo, out, M, CC, CC, nullptr, nullptr, 1.0f);
}